// round 5
// baseline (speedup 1.0000x reference)
#include <cuda_runtime.h>
#include <cstdint>

#define NN 116
#define HH 128
#define NTHREADS 512
#define STR 144   // row stride (floats) for all operand tiles; 144 % 32 == 16

static constexpr size_t SMEM_BYTES = (size_t)(3 * 128 * STR) * 4;

__device__ __forceinline__ float to_tf32(float x) {
    uint32_t u;
    asm("cvt.rna.tf32.f32 %0, %1;" : "=r"(u) : "f"(x));
    return __uint_as_float(u);
}

// Permuted+swizzled float offset of logical element (nrow, k) within a row:
// k = 16*g + 8*s + 4*h + c  ->  16*g + 4*(c ^ (nrow&3)) + 2*s + h
__device__ __forceinline__ int pkoff(int nrow, int k) {
    return (k & ~15) | ((((k & 3) ^ (nrow & 3))) << 2) | (((k >> 3) & 1) << 1) | ((k >> 2) & 1);
}

#define MMA_TF32(d, a0, a1, a2, a3, b0, b1)                                   \
    asm volatile(                                                             \
        "mma.sync.aligned.m16n8k8.row.col.f32.tf32.tf32.f32 "                 \
        "{%0,%1,%2,%3}, {%4,%5,%6,%7}, {%8,%9}, {%0,%1,%2,%3};"               \
        : "+f"(d[0]), "+f"(d[1]), "+f"(d[2]), "+f"(d[3])                      \
        : "r"(__float_as_uint(a0)), "r"(__float_as_uint(a1)),                 \
          "r"(__float_as_uint(a2)), "r"(__float_as_uint(a3)),                 \
          "r"(__float_as_uint(b0)), "r"(__float_as_uint(b1)))

// 128x128x128 GEMM; 16 warps in 4x4 grid, 32(m) x 32(n) warp tiles.
// A: [m][k'] permuted layout. B: [n][k'] permuted layout (i.e. B^T of [k][n]).
__device__ __forceinline__ void gemm128(const float* __restrict__ Aop,
                                        const float* __restrict__ Bop,
                                        float acc[2][4][4],
                                        int wm, int wn, int lane)
{
    const int r = lane >> 2, c = lane & 3;
    const int cx4 = (c ^ (r & 3)) << 2;
    #pragma unroll
    for (int mi = 0; mi < 2; mi++)
        #pragma unroll
        for (int ni = 0; ni < 4; ni++)
            #pragma unroll
            for (int q = 0; q < 4; q++) acc[mi][ni][q] = 0.f;

    const float* a0p = Aop + (wm * 32 + r) * STR + cx4;
    const float* b0p = Bop + (wn * 32 + r) * STR + cx4;

    #pragma unroll 2
    for (int g = 0; g < 8; g++) {
        const int ko = g * 16;
        float4 a[2][2], bv[4];
        #pragma unroll
        for (int mi = 0; mi < 2; mi++) {
            a[mi][0] = *reinterpret_cast<const float4*>(a0p + mi * 16 * STR + ko);
            a[mi][1] = *reinterpret_cast<const float4*>(a0p + (mi * 16 + 8) * STR + ko);
        }
        #pragma unroll
        for (int ni = 0; ni < 4; ni++)
            bv[ni] = *reinterpret_cast<const float4*>(b0p + ni * 8 * STR + ko);

        #pragma unroll
        for (int mi = 0; mi < 2; mi++)
            #pragma unroll
            for (int ni = 0; ni < 4; ni++)
                MMA_TF32(acc[mi][ni], a[mi][0].x, a[mi][1].x, a[mi][0].y, a[mi][1].y,
                         bv[ni].x, bv[ni].y);
        #pragma unroll
        for (int mi = 0; mi < 2; mi++)
            #pragma unroll
            for (int ni = 0; ni < 4; ni++)
                MMA_TF32(acc[mi][ni], a[mi][0].z, a[mi][1].z, a[mi][0].w, a[mi][1].w,
                         bv[ni].z, bv[ni].w);
    }
}

__global__ __launch_bounds__(NTHREADS, 1)
void gcn_mma(const float* __restrict__ ga, const float* __restrict__ gf,
             const float* __restrict__ gW1, const float* __restrict__ gb1,
             const float* __restrict__ gW2, const float* __restrict__ gb2,
             float* __restrict__ gout)
{
    extern __shared__ float sm[];
    float* sA = sm;                  // A_norm    [128][STR] (A-type layout)
    float* sX = sm + 128 * STR;      // f -> h    [128][STR] (A-type layout)
    float* sB = sm + 2 * 128 * STR;  // W1/g/W2/t [128][STR] (B-type: [n][k'])
    __shared__ float sd[128], sb1[128], sb2[128];

    const int tid = threadIdx.x;
    const int wid = tid >> 5, lane = tid & 31;
    const int wm = wid & 3, wn = wid >> 2;
    const int b = blockIdx.x;
    const float* ab = ga + (size_t)b * NN * NN;
    const float* fb = gf + (size_t)b * NN * NN;
    float*       ob = gout + (size_t)b * NN * HH;

    // ---- zero all operand buffers (covers padding) ----
    for (int i = tid; i < 3 * 128 * STR / 4; i += NTHREADS)
        reinterpret_cast<float4*>(sm)[i] = make_float4(0.f, 0.f, 0.f, 0.f);
    if (tid < 128) { sb1[tid] = __ldg(gb1 + tid); sb2[tid] = __ldg(gb2 + tid); }
    __syncthreads();

    // ---- fill |a| (sA), f (sX), W1^T (sB) ----
    for (int idx = tid; idx < NN * NN; idx += NTHREADS) {
        int i = idx / NN, j = idx - i * NN;
        int o = i * STR + pkoff(i, j);
        sA[o] = fabsf(__ldg(ab + idx));
        sX[o] = to_tf32(__ldg(fb + idx));
    }
    for (int idx = tid; idx < NN * HH; idx += NTHREADS) {
        int k = idx >> 7, n = idx & 127;
        sB[n * STR + pkoff(n, k)] = to_tf32(__ldg(gW1 + idx));
    }
    __syncthreads();

    // ---- d = rsqrt(rowsum(|a|) + 1) (permutation is within-row; linear sum ok) ----
    for (int i = wid; i < NN; i += 16) {
        float s = sA[i * STR + lane] + sA[i * STR + lane + 32]
                + sA[i * STR + lane + 64] + sA[i * STR + lane + 96];
        #pragma unroll
        for (int o = 16; o; o >>= 1) s += __shfl_xor_sync(0xffffffffu, s, o);
        if (!lane) sd[i] = rsqrtf(s + 1.0f);
    }
    __syncthreads();

    // ---- A_norm = tf32(d_i d_j (|a| + I)) in place ----
    for (int idx = tid; idx < NN * NN; idx += NTHREADS) {
        int i = idx / NN, j = idx - i * NN;
        int o = i * STR + pkoff(i, j);
        float v = sA[o] + (i == j ? 1.0f : 0.0f);
        sA[o] = to_tf32(sd[i] * sd[j] * v);
    }
    __syncthreads();

    const int r = lane >> 2, c2 = (lane & 3) * 2;
    float acc[2][4][4];

    // ===== G1: g = f @ W1 =====
    gemm128(sX, sB, acc, wm, wn, lane);
    __syncthreads();                          // all warps done reading W1
    #pragma unroll
    for (int mi = 0; mi < 2; mi++)
        #pragma unroll
        for (int ni = 0; ni < 4; ni++) {
            int row = wm * 32 + mi * 16 + r, col = wn * 32 + ni * 8 + c2;
            sB[col * STR + pkoff(col, row)]           = to_tf32(acc[mi][ni][0]);
            sB[(col + 1) * STR + pkoff(col + 1, row)] = to_tf32(acc[mi][ni][1]);
            sB[col * STR + pkoff(col, row + 8)]           = to_tf32(acc[mi][ni][2]);
            sB[(col + 1) * STR + pkoff(col + 1, row + 8)] = to_tf32(acc[mi][ni][3]);
        }
    __syncthreads();

    // ===== G2: h = relu(A_norm @ g + b1) =====
    gemm128(sA, sB, acc, wm, wn, lane);
    __syncthreads();                          // all warps done reading g
    #pragma unroll
    for (int mi = 0; mi < 2; mi++)
        #pragma unroll
        for (int ni = 0; ni < 4; ni++) {
            int row = wm * 32 + mi * 16 + r, col = wn * 32 + ni * 8 + c2;
            sX[row * STR + pkoff(row, col)]     = to_tf32(fmaxf(acc[mi][ni][0] + sb1[col], 0.f));
            sX[row * STR + pkoff(row, col + 1)] = to_tf32(fmaxf(acc[mi][ni][1] + sb1[col + 1], 0.f));
            sX[(row + 8) * STR + pkoff(row + 8, col)]     = to_tf32(fmaxf(acc[mi][ni][2] + sb1[col], 0.f));
            sX[(row + 8) * STR + pkoff(row + 8, col + 1)] = to_tf32(fmaxf(acc[mi][ni][3] + sb1[col + 1], 0.f));
        }
    for (int idx = tid; idx < HH * HH; idx += NTHREADS) {
        int k = idx >> 7, n = idx & 127;
        sB[n * STR + pkoff(n, k)] = to_tf32(__ldg(gW2 + idx));
    }
    __syncthreads();

    // ===== G3: t = h @ W2 =====
    gemm128(sX, sB, acc, wm, wn, lane);
    __syncthreads();                          // all warps done reading W2
    #pragma unroll
    for (int mi = 0; mi < 2; mi++)
        #pragma unroll
        for (int ni = 0; ni < 4; ni++) {
            int row = wm * 32 + mi * 16 + r, col = wn * 32 + ni * 8 + c2;
            sB[col * STR + pkoff(col, row)]           = to_tf32(acc[mi][ni][0]);
            sB[(col + 1) * STR + pkoff(col + 1, row)] = to_tf32(acc[mi][ni][1]);
            sB[col * STR + pkoff(col, row + 8)]           = to_tf32(acc[mi][ni][2]);
            sB[(col + 1) * STR + pkoff(col + 1, row + 8)] = to_tf32(acc[mi][ni][3]);
        }
    __syncthreads();

    // ===== G4: out = relu(A_norm @ t + b2) =====
    gemm128(sA, sB, acc, wm, wn, lane);
    #pragma unroll
    for (int mi = 0; mi < 2; mi++)
        #pragma unroll
        for (int ni = 0; ni < 4; ni++) {
            int row = wm * 32 + mi * 16 + r, col = wn * 32 + ni * 8 + c2;
            if (row < NN) {
                float2 v0 = make_float2(fmaxf(acc[mi][ni][0] + sb2[col], 0.f),
                                        fmaxf(acc[mi][ni][1] + sb2[col + 1], 0.f));
                *reinterpret_cast<float2*>(ob + (size_t)row * HH + col) = v0;
            }
            if (row + 8 < NN) {
                float2 v1 = make_float2(fmaxf(acc[mi][ni][2] + sb2[col], 0.f),
                                        fmaxf(acc[mi][ni][3] + sb2[col + 1], 0.f));
                *reinterpret_cast<float2*>(ob + (size_t)(row + 8) * HH + col) = v1;
            }
        }
}

extern "C" void kernel_launch(void* const* d_in, const int* in_sizes, int n_in,
                              void* d_out, int out_size)
{
    const float* a  = (const float*)d_in[0];
    const float* f  = (const float*)d_in[1];
    const float* W1 = (const float*)d_in[2];
    const float* b1 = (const float*)d_in[3];
    const float* W2 = (const float*)d_in[4];
    const float* b2 = (const float*)d_in[5];
    float* out = (float*)d_out;

    int batch = in_sizes[0] / (NN * NN);

    cudaFuncSetAttribute(gcn_mma, cudaFuncAttributeMaxDynamicSharedMemorySize, (int)SMEM_BYTES);
    gcn_mma<<<batch, NTHREADS, SMEM_BYTES>>>(a, f, W1, b1, W2, b2, out);
}

// round 6
// speedup vs baseline: 1.3418x; 1.3418x over previous
#include <cuda_runtime.h>
#include <cstdint>

#define NN 116
#define HH 128
#define NTHREADS 512
#define STR_A 132     // A-operand row stride (floats): banks (4r+c)%32 all-distinct
#define STR_B 136     // B-operand row stride (floats): banks (8c+r)%32 all-distinct

static constexpr size_t SMEM_BYTES = (size_t)(2 * 128 * STR_A + 128 * STR_B) * 4;

__device__ __forceinline__ float to_tf32(float x) {
    uint32_t u;
    asm("cvt.rna.tf32.f32 %0, %1;" : "=r"(u) : "f"(x));
    return __uint_as_float(u);
}

#define MMA_TF32(d, a, b)                                                     \
    asm volatile(                                                             \
        "mma.sync.aligned.m16n8k8.row.col.f32.tf32.tf32.f32 "                 \
        "{%0,%1,%2,%3}, {%4,%5,%6,%7}, {%8,%9}, {%0,%1,%2,%3};"               \
        : "+f"(d[0]), "+f"(d[1]), "+f"(d[2]), "+f"(d[3])                      \
        : "r"(a[0]), "r"(a[1]), "r"(a[2]), "r"(a[3]), "r"(b[0]), "r"(b[1]))

// 128x128x128 GEMM, 16 warps in a 4x4 grid; warp tile 32(m) x 32(n).
// Fully unrolled k-loop with double-buffered fragment prefetch: fragments for
// step ks+1 are loaded while step ks's 8 independent MMAs issue.
__device__ __forceinline__ void gemm128(const float* __restrict__ Aop,
                                        const float* __restrict__ Bop,
                                        float acc[2][4][4],
                                        int wm, int wn, int lane)
{
    const int r = lane >> 2, c = lane & 3;
    #pragma unroll
    for (int mi = 0; mi < 2; mi++)
        #pragma unroll
        for (int ni = 0; ni < 4; ni++)
            #pragma unroll
            for (int q = 0; q < 4; q++) acc[mi][ni][q] = 0.f;

    const float* apb = Aop + (wm * 32 + r) * STR_A + c;
    const float* bpb = Bop + c * STR_B + wn * 32 + r;

    uint32_t fa[2][2][4], fb[2][4][2];

    // prologue: load k-step 0 into buffer 0
    #pragma unroll
    for (int mi = 0; mi < 2; mi++) {
        const float* ap = apb + mi * 16 * STR_A;
        fa[0][mi][0] = __float_as_uint(ap[0]);
        fa[0][mi][1] = __float_as_uint(ap[8 * STR_A]);
        fa[0][mi][2] = __float_as_uint(ap[4]);
        fa[0][mi][3] = __float_as_uint(ap[8 * STR_A + 4]);
    }
    #pragma unroll
    for (int ni = 0; ni < 4; ni++) {
        const float* bp = bpb + ni * 8;
        fb[0][ni][0] = __float_as_uint(bp[0]);
        fb[0][ni][1] = __float_as_uint(bp[4 * STR_B]);
    }

    #pragma unroll
    for (int ks = 0; ks < 16; ks++) {
        const int cur = ks & 1, nxt = cur ^ 1;
        if (ks < 15) {
            const int k0 = (ks + 1) * 8;
            #pragma unroll
            for (int mi = 0; mi < 2; mi++) {
                const float* ap = apb + mi * 16 * STR_A + k0;
                fa[nxt][mi][0] = __float_as_uint(ap[0]);
                fa[nxt][mi][1] = __float_as_uint(ap[8 * STR_A]);
                fa[nxt][mi][2] = __float_as_uint(ap[4]);
                fa[nxt][mi][3] = __float_as_uint(ap[8 * STR_A + 4]);
            }
            #pragma unroll
            for (int ni = 0; ni < 4; ni++) {
                const float* bp = bpb + k0 * STR_B + ni * 8;
                fb[nxt][ni][0] = __float_as_uint(bp[0]);
                fb[nxt][ni][1] = __float_as_uint(bp[4 * STR_B]);
            }
        }
        #pragma unroll
        for (int mi = 0; mi < 2; mi++)
            #pragma unroll
            for (int ni = 0; ni < 4; ni++)
                MMA_TF32(acc[mi][ni], fa[cur][mi], fb[cur][ni]);
    }
}

__global__ __launch_bounds__(NTHREADS, 1)
void gcn_mma(const float* __restrict__ ga, const float* __restrict__ gf,
             const float* __restrict__ gW1, const float* __restrict__ gb1,
             const float* __restrict__ gW2, const float* __restrict__ gb2,
             float* __restrict__ gout)
{
    extern __shared__ float sm[];
    float* sA = sm;                          // A_norm    [128][STR_A]
    float* sX = sm + 128 * STR_A;            // f -> h    [128][STR_A]
    float* sB = sm + 2 * 128 * STR_A;        // W1/g/W2/t [128][STR_B]
    __shared__ float sd[128], sb1[128], sb2[128];

    const int tid = threadIdx.x;
    const int wid = tid >> 5, lane = tid & 31;
    const int wm = wid & 3, wn = wid >> 2;   // 4x4 warp grid -> 32x32 tiles
    const int b = blockIdx.x;
    const float* ab = ga + (size_t)b * NN * NN;
    const float* fb = gf + (size_t)b * NN * NN;
    float*       ob = gout + (size_t)b * NN * HH;

    // ---- zero pads (full buffers) ----
    for (int i = tid; i < 2 * 128 * STR_A + 128 * STR_B; i += NTHREADS) sm[i] = 0.f;
    if (tid < 128) { sb1[tid] = __ldg(gb1 + tid); sb2[tid] = __ldg(gb2 + tid); }
    __syncthreads();

    // ---- fill |a|, f(tf32), W1(tf32) ----
    for (int idx = tid; idx < NN * NN; idx += NTHREADS) {
        int i = idx / NN, j = idx - i * NN;
        sA[i * STR_A + j] = fabsf(__ldg(ab + idx));
        sX[i * STR_A + j] = to_tf32(__ldg(fb + idx));
    }
    for (int idx = tid; idx < NN * HH; idx += NTHREADS) {
        int k = idx >> 7, n = idx & 127;
        sB[k * STR_B + n] = to_tf32(__ldg(gW1 + idx));
    }
    __syncthreads();

    // ---- d = rsqrt(rowsum(|a|) + 1) ----
    for (int i = wid; i < NN; i += 16) {
        float s = sA[i * STR_A + lane] + sA[i * STR_A + lane + 32]
                + sA[i * STR_A + lane + 64] + sA[i * STR_A + lane + 96];
        #pragma unroll
        for (int o = 16; o; o >>= 1) s += __shfl_xor_sync(0xffffffffu, s, o);
        if (!lane) sd[i] = rsqrtf(s + 1.0f);
    }
    __syncthreads();

    // ---- A_norm = tf32(d_i d_j (|a| + I)) in place ----
    for (int idx = tid; idx < NN * NN; idx += NTHREADS) {
        int i = idx / NN, j = idx - i * NN;
        float v = sA[i * STR_A + j] + (i == j ? 1.0f : 0.0f);
        sA[i * STR_A + j] = to_tf32(sd[i] * sd[j] * v);
    }
    __syncthreads();

    const int r = lane >> 2, c2 = (lane & 3) * 2;
    float acc[2][4][4];

    // ===== G1: g = f @ W1 =====
    gemm128(sX, sB, acc, wm, wn, lane);
    __syncthreads();                          // all warps done reading W1
    #pragma unroll
    for (int mi = 0; mi < 2; mi++)
        #pragma unroll
        for (int ni = 0; ni < 4; ni++) {
            int row = wm * 32 + mi * 16 + r, col = wn * 32 + ni * 8 + c2;
            sB[row * STR_B + col]           = to_tf32(acc[mi][ni][0]);
            sB[row * STR_B + col + 1]       = to_tf32(acc[mi][ni][1]);
            sB[(row + 8) * STR_B + col]     = to_tf32(acc[mi][ni][2]);
            sB[(row + 8) * STR_B + col + 1] = to_tf32(acc[mi][ni][3]);
        }
    __syncthreads();

    // ===== G2: h = relu(A_norm @ g + b1) =====
    gemm128(sA, sB, acc, wm, wn, lane);
    __syncthreads();                          // all warps done reading g
    #pragma unroll
    for (int mi = 0; mi < 2; mi++)
        #pragma unroll
        for (int ni = 0; ni < 4; ni++) {
            int row = wm * 32 + mi * 16 + r, col = wn * 32 + ni * 8 + c2;
            sX[row * STR_A + col]           = to_tf32(fmaxf(acc[mi][ni][0] + sb1[col], 0.f));
            sX[row * STR_A + col + 1]       = to_tf32(fmaxf(acc[mi][ni][1] + sb1[col + 1], 0.f));
            sX[(row + 8) * STR_A + col]     = to_tf32(fmaxf(acc[mi][ni][2] + sb1[col], 0.f));
            sX[(row + 8) * STR_A + col + 1] = to_tf32(fmaxf(acc[mi][ni][3] + sb1[col + 1], 0.f));
        }
    for (int idx = tid; idx < HH * HH; idx += NTHREADS) {
        int k = idx >> 7, n = idx & 127;
        sB[k * STR_B + n] = to_tf32(__ldg(gW2 + idx));
    }
    __syncthreads();

    // ===== G3: t = h @ W2 =====
    gemm128(sX, sB, acc, wm, wn, lane);
    __syncthreads();                          // all warps done reading W2
    #pragma unroll
    for (int mi = 0; mi < 2; mi++)
        #pragma unroll
        for (int ni = 0; ni < 4; ni++) {
            int row = wm * 32 + mi * 16 + r, col = wn * 32 + ni * 8 + c2;
            sB[row * STR_B + col]           = to_tf32(acc[mi][ni][0]);
            sB[row * STR_B + col + 1]       = to_tf32(acc[mi][ni][1]);
            sB[(row + 8) * STR_B + col]     = to_tf32(acc[mi][ni][2]);
            sB[(row + 8) * STR_B + col + 1] = to_tf32(acc[mi][ni][3]);
        }
    __syncthreads();

    // ===== G4: out = relu(A_norm @ t + b2) =====
    gemm128(sA, sB, acc, wm, wn, lane);
    #pragma unroll
    for (int mi = 0; mi < 2; mi++)
        #pragma unroll
        for (int ni = 0; ni < 4; ni++) {
            int row = wm * 32 + mi * 16 + r, col = wn * 32 + ni * 8 + c2;
            if (row < NN) {
                float2 v0 = make_float2(fmaxf(acc[mi][ni][0] + sb2[col], 0.f),
                                        fmaxf(acc[mi][ni][1] + sb2[col + 1], 0.f));
                *reinterpret_cast<float2*>(ob + (size_t)row * HH + col) = v0;
            }
            if (row + 8 < NN) {
                float2 v1 = make_float2(fmaxf(acc[mi][ni][2] + sb2[col], 0.f),
                                        fmaxf(acc[mi][ni][3] + sb2[col + 1], 0.f));
                *reinterpret_cast<float2*>(ob + (size_t)(row + 8) * HH + col) = v1;
            }
        }
}

extern "C" void kernel_launch(void* const* d_in, const int* in_sizes, int n_in,
                              void* d_out, int out_size)
{
    const float* a  = (const float*)d_in[0];
    const float* f  = (const float*)d_in[1];
    const float* W1 = (const float*)d_in[2];
    const float* b1 = (const float*)d_in[3];
    const float* W2 = (const float*)d_in[4];
    const float* b2 = (const float*)d_in[5];
    float* out = (float*)d_out;

    int batch = in_sizes[0] / (NN * NN);

    cudaFuncSetAttribute(gcn_mma, cudaFuncAttributeMaxDynamicSharedMemorySize, (int)SMEM_BYTES);
    gcn_mma<<<batch, NTHREADS, SMEM_BYTES>>>(a, f, W1, b1, W2, b2, out);
}

// round 7
// speedup vs baseline: 1.3721x; 1.0226x over previous
#include <cuda_runtime.h>
#include <cstdint>

#define NN 116
#define HH 128
#define NTHREADS 512
#define STR_A 132     // A-operand row stride (floats): banks (4r+c)%32 all-distinct
#define STR_B 136     // B-operand row stride (floats): banks (8c+r)%32 all-distinct

static constexpr size_t SMEM_BYTES = (size_t)(2 * 128 * STR_A + 128 * STR_B) * 4;

__device__ __forceinline__ float to_tf32(float x) {
    uint32_t u;
    asm("cvt.rna.tf32.f32 %0, %1;" : "=r"(u) : "f"(x));
    return __uint_as_float(u);
}
__device__ __forceinline__ uint32_t smem_u32(const void* p) {
    uint32_t a;
    asm("{ .reg .u64 t; cvta.to.shared.u64 t, %1; cvt.u32.u64 %0, t; }" : "=r"(a) : "l"(p));
    return a;
}

#define LDS32(dst, addr) \
    asm volatile("ld.shared.b32 %0, [%1];" : "=r"(dst) : "r"(addr))

#define MMA_TF32(d, a, b)                                                     \
    asm volatile(                                                             \
        "mma.sync.aligned.m16n8k8.row.col.f32.tf32.tf32.f32 "                 \
        "{%0,%1,%2,%3}, {%4,%5,%6,%7}, {%8,%9}, {%0,%1,%2,%3};"               \
        : "+f"(d[0]), "+f"(d[1]), "+f"(d[2]), "+f"(d[3])                      \
        : "r"(a[0]), "r"(a[1]), "r"(a[2]), "r"(a[3]), "r"(b[0]), "r"(b[1]))

// 128x128xK GEMM, 16 warps 4x4 grid, 32(m)x32(n) warp tiles.
// Double-buffered fragments with ENFORCED fine-grain LDS/MMA interleave:
// before each MMA pair, 4 volatile ld.shared prefetch the next k-step.
template <int KSTEPS>
__device__ __forceinline__ void gemm128(const float* __restrict__ Aop,
                                        const float* __restrict__ Bop,
                                        float acc[2][4][4],
                                        int wm, int wn, int lane)
{
    const int r = lane >> 2, c = lane & 3;
    #pragma unroll
    for (int mi = 0; mi < 2; mi++)
        #pragma unroll
        for (int ni = 0; ni < 4; ni++)
            #pragma unroll
            for (int q = 0; q < 4; q++) acc[mi][ni][q] = 0.f;

    const uint32_t aA = smem_u32(Aop + (wm * 32 + r) * STR_A + c);
    const uint32_t aB = smem_u32(Bop + c * STR_B + wn * 32 + r);

    uint32_t fa[2][2][4], fb[2][4][2];

    // A-element byte offsets within a k-step: {k, k+8rows, k+4, k+8rows+4}
    const int AO0 = 0, AO1 = 8 * STR_A * 4, AO2 = 16, AO3 = 8 * STR_A * 4 + 16;

    // prologue: k-step 0 -> buffer 0
    #pragma unroll
    for (int mi = 0; mi < 2; mi++) {
        const uint32_t ab = aA + mi * 16 * STR_A * 4;
        LDS32(fa[0][mi][0], ab + AO0);
        LDS32(fa[0][mi][1], ab + AO1);
        LDS32(fa[0][mi][2], ab + AO2);
        LDS32(fa[0][mi][3], ab + AO3);
    }
    #pragma unroll
    for (int ni = 0; ni < 4; ni++) {
        LDS32(fb[0][ni][0], aB + ni * 32);
        LDS32(fb[0][ni][1], aB + ni * 32 + 4 * STR_B * 4);
    }

    #pragma unroll
    for (int ks = 0; ks < KSTEPS; ks++) {
        const int cur = ks & 1, nxt = cur ^ 1;
        const uint32_t nkA = aA + (ks + 1) * 32;             // next k0 (floats*4)
        const uint32_t nkB = aB + (ks + 1) * 8 * STR_B * 4;
        #pragma unroll
        for (int ni = 0; ni < 4; ni++) {
            if (ks < KSTEPS - 1) {
                // 2 B-frag loads for column ni of next step
                LDS32(fb[nxt][ni][0], nkB + ni * 32);
                LDS32(fb[nxt][ni][1], nkB + ni * 32 + 4 * STR_B * 4);
                // 2 A-frag loads: ni -> (mi2 = ni>>1, elems 2*(ni&1), +1)
                const int mi2 = ni >> 1;
                const uint32_t ab = nkA + mi2 * 16 * STR_A * 4;
                if ((ni & 1) == 0) {
                    LDS32(fa[nxt][mi2][0], ab + AO0);
                    LDS32(fa[nxt][mi2][1], ab + AO1);
                } else {
                    LDS32(fa[nxt][mi2][2], ab + AO2);
                    LDS32(fa[nxt][mi2][3], ab + AO3);
                }
            }
            MMA_TF32(acc[0][ni], fa[cur][0], fb[cur][ni]);
            MMA_TF32(acc[1][ni], fa[cur][1], fb[cur][ni]);
        }
    }
}

__global__ __launch_bounds__(NTHREADS, 1)
void gcn_mma(const float* __restrict__ ga, const float* __restrict__ gf,
             const float* __restrict__ gW1, const float* __restrict__ gb1,
             const float* __restrict__ gW2, const float* __restrict__ gb2,
             float* __restrict__ gout)
{
    extern __shared__ float sm[];
    float* sA = sm;                          // A_norm    [128][STR_A]
    float* sX = sm + 128 * STR_A;            // f -> h    [128][STR_A]
    float* sB = sm + 2 * 128 * STR_A;        // W1/g/W2/t [128][STR_B]
    __shared__ float sd[128], sb1[128], sb2[128];

    const int tid = threadIdx.x;
    const int wid = tid >> 5, lane = tid & 31;
    const int wm = wid & 3, wn = wid >> 2;   // 4x4 warp grid -> 32x32 tiles
    const int b = blockIdx.x;
    const float* ab = ga + (size_t)b * NN * NN;
    const float* fb_g = gf + (size_t)b * NN * NN;
    float*       ob = gout + (size_t)b * NN * HH;

    // ---- zero buffers (float4; sizes divisible by 4) ----
    for (int i = tid; i < (2 * 128 * STR_A + 128 * STR_B) / 4; i += NTHREADS)
        reinterpret_cast<float4*>(sm)[i] = make_float4(0.f, 0.f, 0.f, 0.f);
    if (tid < 128) { sb1[tid] = __ldg(gb1 + tid); sb2[tid] = __ldg(gb2 + tid); }
    __syncthreads();

    // ---- fill |a|, f(tf32), W1(tf32) ----
    for (int idx = tid; idx < NN * NN; idx += NTHREADS) {
        int i = idx / NN, j = idx - i * NN;
        sA[i * STR_A + j] = fabsf(__ldg(ab + idx));
        sX[i * STR_A + j] = to_tf32(__ldg(fb_g + idx));
    }
    for (int idx = tid; idx < NN * HH; idx += NTHREADS) {
        int k = idx >> 7, n = idx & 127;
        sB[k * STR_B + n] = to_tf32(__ldg(gW1 + idx));
    }
    __syncthreads();

    // ---- d = rsqrt(rowsum(|a|) + 1) ----
    for (int i = wid; i < NN; i += 16) {
        float s = sA[i * STR_A + lane] + sA[i * STR_A + lane + 32]
                + sA[i * STR_A + lane + 64] + sA[i * STR_A + lane + 96];
        #pragma unroll
        for (int o = 16; o; o >>= 1) s += __shfl_xor_sync(0xffffffffu, s, o);
        if (!lane) sd[i] = rsqrtf(s + 1.0f);
    }
    __syncthreads();

    // ---- A_norm = tf32(d_i d_j (|a| + I)) in place ----
    for (int idx = tid; idx < NN * NN; idx += NTHREADS) {
        int i = idx / NN, j = idx - i * NN;
        float v = sA[i * STR_A + j] + (i == j ? 1.0f : 0.0f);
        sA[i * STR_A + j] = to_tf32(sd[i] * sd[j] * v);
    }
    __syncthreads();

    const int r = lane >> 2, c2 = (lane & 3) * 2;
    float acc[2][4][4];

    // ===== G1: g = f @ W1  (K = 120) =====
    gemm128<15>(sX, sB, acc, wm, wn, lane);
    __syncthreads();                          // all warps done reading W1
    #pragma unroll
    for (int mi = 0; mi < 2; mi++)
        #pragma unroll
        for (int ni = 0; ni < 4; ni++) {
            int row = wm * 32 + mi * 16 + r, col = wn * 32 + ni * 8 + c2;
            sB[row * STR_B + col]           = to_tf32(acc[mi][ni][0]);
            sB[row * STR_B + col + 1]       = to_tf32(acc[mi][ni][1]);
            sB[(row + 8) * STR_B + col]     = to_tf32(acc[mi][ni][2]);
            sB[(row + 8) * STR_B + col + 1] = to_tf32(acc[mi][ni][3]);
        }
    __syncthreads();

    // ===== G2: h = relu(A_norm @ g + b1)  (K = 120) =====
    gemm128<15>(sA, sB, acc, wm, wn, lane);
    __syncthreads();                          // all warps done reading g
    // W2 -> sB first (overlap L2 latency with epi stores below)
    for (int idx = tid; idx < HH * HH; idx += NTHREADS) {
        int k = idx >> 7, n = idx & 127;
        sB[k * STR_B + n] = to_tf32(__ldg(gW2 + idx));
    }
    #pragma unroll
    for (int mi = 0; mi < 2; mi++)
        #pragma unroll
        for (int ni = 0; ni < 4; ni++) {
            int row = wm * 32 + mi * 16 + r, col = wn * 32 + ni * 8 + c2;
            sX[row * STR_A + col]           = to_tf32(fmaxf(acc[mi][ni][0] + sb1[col], 0.f));
            sX[row * STR_A + col + 1]       = to_tf32(fmaxf(acc[mi][ni][1] + sb1[col + 1], 0.f));
            sX[(row + 8) * STR_A + col]     = to_tf32(fmaxf(acc[mi][ni][2] + sb1[col], 0.f));
            sX[(row + 8) * STR_A + col + 1] = to_tf32(fmaxf(acc[mi][ni][3] + sb1[col + 1], 0.f));
        }
    __syncthreads();

    // ===== G3: t = h @ W2  (K = 128) =====
    gemm128<16>(sX, sB, acc, wm, wn, lane);
    __syncthreads();                          // all warps done reading W2
    #pragma unroll
    for (int mi = 0; mi < 2; mi++)
        #pragma unroll
        for (int ni = 0; ni < 4; ni++) {
            int row = wm * 32 + mi * 16 + r, col = wn * 32 + ni * 8 + c2;
            sB[row * STR_B + col]           = to_tf32(acc[mi][ni][0]);
            sB[row * STR_B + col + 1]       = to_tf32(acc[mi][ni][1]);
            sB[(row + 8) * STR_B + col]     = to_tf32(acc[mi][ni][2]);
            sB[(row + 8) * STR_B + col + 1] = to_tf32(acc[mi][ni][3]);
        }
    __syncthreads();

    // ===== G4: out = relu(A_norm @ t + b2)  (K = 120) =====
    gemm128<15>(sA, sB, acc, wm, wn, lane);
    #pragma unroll
    for (int mi = 0; mi < 2; mi++)
        #pragma unroll
        for (int ni = 0; ni < 4; ni++) {
            int row = wm * 32 + mi * 16 + r, col = wn * 32 + ni * 8 + c2;
            if (row < NN) {
                float2 v0 = make_float2(fmaxf(acc[mi][ni][0] + sb2[col], 0.f),
                                        fmaxf(acc[mi][ni][1] + sb2[col + 1], 0.f));
                *reinterpret_cast<float2*>(ob + (size_t)row * HH + col) = v0;
            }
            if (row + 8 < NN) {
                float2 v1 = make_float2(fmaxf(acc[mi][ni][2] + sb2[col], 0.f),
                                        fmaxf(acc[mi][ni][3] + sb2[col + 1], 0.f));
                *reinterpret_cast<float2*>(ob + (size_t)(row + 8) * HH + col) = v1;
            }
        }
}

extern "C" void kernel_launch(void* const* d_in, const int* in_sizes, int n_in,
                              void* d_out, int out_size)
{
    const float* a  = (const float*)d_in[0];
    const float* f  = (const float*)d_in[1];
    const float* W1 = (const float*)d_in[2];
    const float* b1 = (const float*)d_in[3];
    const float* W2 = (const float*)d_in[4];
    const float* b2 = (const float*)d_in[5];
    float* out = (float*)d_out;

    int batch = in_sizes[0] / (NN * NN);

    cudaFuncSetAttribute(gcn_mma, cudaFuncAttributeMaxDynamicSharedMemorySize, (int)SMEM_BYTES);
    gcn_mma<<<batch, NTHREADS, SMEM_BYTES>>>(a, f, W1, b1, W2, b2, out);
}

// round 8
// speedup vs baseline: 1.8331x; 1.3360x over previous
#include <cuda_runtime.h>
#include <cuda_fp16.h>
#include <cstdint>

#define NN 116
#define HH 128
#define NTHREADS 256
#define STR 136            // row stride in HALFS; (STR/2)%32==4 -> bank-clean frags

static constexpr size_t SMEM_BYTES = (size_t)(3 * 128 * STR) * sizeof(__half);  // 104448

__device__ __forceinline__ uint32_t smem_u32(const void* p) {
    uint32_t a;
    asm("{ .reg .u64 t; cvta.to.shared.u64 t, %1; cvt.u32.u64 %0, t; }" : "=r"(a) : "l"(p));
    return a;
}
#define LDS32(dst, addr) \
    asm volatile("ld.shared.b32 %0, [%1];" : "=r"(dst) : "r"(addr))

#define MMA_F16(d, a, b)                                                      \
    asm volatile(                                                             \
        "mma.sync.aligned.m16n8k16.row.col.f32.f16.f16.f32 "                  \
        "{%0,%1,%2,%3}, {%4,%5,%6,%7}, {%8,%9}, {%0,%1,%2,%3};"               \
        : "+f"(d[0]), "+f"(d[1]), "+f"(d[2]), "+f"(d[3])                      \
        : "r"(a[0]), "r"(a[1]), "r"(a[2]), "r"(a[3]), "r"(b[0]), "r"(b[1]))

// 128x128x128 fp16 GEMM; 8 warps in 2x4 grid; warp tile 64(m) x 32(n).
// A: [m][k] halfs, B: [n][k] halfs (row.col form). 24 LDS32 + 16 MMA / k-step.
__device__ __forceinline__ void gemm_h(const __half* __restrict__ Aop,
                                       const __half* __restrict__ Bop,
                                       float acc[4][4][4],
                                       int wm, int wn, int lane)
{
    const int r = lane >> 2, c = lane & 3;
    #pragma unroll
    for (int mi = 0; mi < 4; mi++)
        #pragma unroll
        for (int ni = 0; ni < 4; ni++)
            #pragma unroll
            for (int q = 0; q < 4; q++) acc[mi][ni][q] = 0.f;

    const uint32_t aA = smem_u32(Aop + (wm * 64 + r) * STR + 2 * c);
    const uint32_t aB = smem_u32(Bop + (wn * 32 + r) * STR + 2 * c);
    const uint32_t ROW8 = 8 * STR * 2;   // 8 rows in bytes

    #pragma unroll
    for (int ks = 0; ks < 8; ks++) {
        const uint32_t kb = ks * 32;     // 16 halfs = 32 bytes
        uint32_t fa[4][4], fb[4][2];
        #pragma unroll
        for (int mi = 0; mi < 4; mi++) {
            const uint32_t ab = aA + mi * 16 * STR * 2 + kb;
            LDS32(fa[mi][0], ab);
            LDS32(fa[mi][1], ab + ROW8);
            LDS32(fa[mi][2], ab + 16);
            LDS32(fa[mi][3], ab + ROW8 + 16);
        }
        #pragma unroll
        for (int ni = 0; ni < 4; ni++) {
            const uint32_t bb = aB + ni * 8 * STR * 2 + kb;
            LDS32(fb[ni][0], bb);
            LDS32(fb[ni][1], bb + 16);
        }
        #pragma unroll
        for (int mi = 0; mi < 4; mi++)
            #pragma unroll
            for (int ni = 0; ni < 4; ni++)
                MMA_F16(acc[mi][ni], fa[mi], fb[ni]);
    }
}

__global__ __launch_bounds__(NTHREADS, 2)
void gcn_mma(const float* __restrict__ ga, const float* __restrict__ gf,
             const float* __restrict__ gW1, const float* __restrict__ gb1,
             const float* __restrict__ gW2, const float* __restrict__ gb2,
             float* __restrict__ gout)
{
    extern __shared__ __half sh[];
    __half* sA = sh;                  // A_norm    [128][STR]  (A-layout [m][k])
    __half* sX = sh + 128 * STR;      // f -> h    [128][STR]  (A-layout)
    __half* sB = sh + 2 * 128 * STR;  // W1/g/W2/t [128][STR]  (B-layout [n][k])
    __shared__ float sd[128], sb1[128], sb2[128];

    const int tid = threadIdx.x;
    const int wid = tid >> 5, lane = tid & 31;
    const int wm = wid & 1, wn = wid >> 1;   // 2x4 warp grid -> 64x32 tiles
    const int b = blockIdx.x;
    const float* ab = ga + (size_t)b * NN * NN;
    const float* fg = gf + (size_t)b * NN * NN;
    float*       ob = gout + (size_t)b * NN * HH;

    // ---- zero all operand buffers (uint4; 104448/16 = 6528) ----
    for (int i = tid; i < 6528; i += NTHREADS)
        reinterpret_cast<uint4*>(sh)[i] = make_uint4(0u, 0u, 0u, 0u);
    if (tid < 128) { sb1[tid] = __ldg(gb1 + tid); sb2[tid] = __ldg(gb2 + tid); }

    // ---- pass 1: rowsums of |a| straight from gmem -> d ----
    for (int row = wid; row < NN; row += 8) {
        const float* rp = ab + row * NN;
        float s = 0.f;
        #pragma unroll
        for (int jj = 0; jj < 4; jj++) {
            int j = lane + jj * 32;
            if (j < NN) s += fabsf(__ldg(rp + j));
        }
        #pragma unroll
        for (int o = 16; o; o >>= 1) s += __shfl_xor_sync(0xffffffffu, s, o);
        if (!lane) sd[row] = rsqrtf(s + 1.0f);
    }
    __syncthreads();

    // ---- pass 2: A_norm(half), f(half), W1(half, [n][k]) ----
    for (int idx = tid; idx < NN * NN; idx += NTHREADS) {
        int i = idx / NN, j = idx - i * NN;
        float v = fabsf(__ldg(ab + idx)) + (i == j ? 1.0f : 0.0f);
        sA[i * STR + j] = __float2half_rn(sd[i] * sd[j] * v);
        sX[i * STR + j] = __float2half_rn(__ldg(fg + idx));
    }
    for (int idx = tid; idx < NN * HH; idx += NTHREADS) {
        int k = idx >> 7, n = idx & 127;
        sB[n * STR + k] = __float2half_rn(__ldg(gW1 + idx));
    }
    __syncthreads();

    const int r = lane >> 2, c2 = (lane & 3) * 2;
    float acc[4][4][4];

    // ===== G1: g = f @ W1 =====
    gemm_h(sX, sB, acc, wm, wn, lane);
    __syncthreads();                          // all warps done reading W1
    #pragma unroll
    for (int mi = 0; mi < 4; mi++)
        #pragma unroll
        for (int ni = 0; ni < 4; ni++) {
            int row = wm * 64 + mi * 16 + r, col = wn * 32 + ni * 8 + c2;
            sB[col * STR + row]           = __float2half_rn(acc[mi][ni][0]);
            sB[(col + 1) * STR + row]     = __float2half_rn(acc[mi][ni][1]);
            sB[col * STR + row + 8]       = __float2half_rn(acc[mi][ni][2]);
            sB[(col + 1) * STR + row + 8] = __float2half_rn(acc[mi][ni][3]);
        }
    __syncthreads();

    // ===== G2: h = relu(A_norm @ g + b1) =====
    gemm_h(sA, sB, acc, wm, wn, lane);
    __syncthreads();                          // all warps done reading g
    #pragma unroll
    for (int mi = 0; mi < 4; mi++)
        #pragma unroll
        for (int ni = 0; ni < 4; ni++) {
            int row = wm * 64 + mi * 16 + r, col = wn * 32 + ni * 8 + c2;
            *reinterpret_cast<__half2*>(sX + row * STR + col) =
                __floats2half2_rn(fmaxf(acc[mi][ni][0] + sb1[col], 0.f),
                                  fmaxf(acc[mi][ni][1] + sb1[col + 1], 0.f));
            *reinterpret_cast<__half2*>(sX + (row + 8) * STR + col) =
                __floats2half2_rn(fmaxf(acc[mi][ni][2] + sb1[col], 0.f),
                                  fmaxf(acc[mi][ni][3] + sb1[col + 1], 0.f));
        }
    for (int idx = tid; idx < HH * HH; idx += NTHREADS) {
        int k = idx >> 7, n = idx & 127;
        sB[n * STR + k] = __float2half_rn(__ldg(gW2 + idx));
    }
    __syncthreads();

    // ===== G3: t = h @ W2 =====
    gemm_h(sX, sB, acc, wm, wn, lane);
    __syncthreads();                          // all warps done reading W2
    #pragma unroll
    for (int mi = 0; mi < 4; mi++)
        #pragma unroll
        for (int ni = 0; ni < 4; ni++) {
            int row = wm * 64 + mi * 16 + r, col = wn * 32 + ni * 8 + c2;
            sB[col * STR + row]           = __float2half_rn(acc[mi][ni][0]);
            sB[(col + 1) * STR + row]     = __float2half_rn(acc[mi][ni][1]);
            sB[col * STR + row + 8]       = __float2half_rn(acc[mi][ni][2]);
            sB[(col + 1) * STR + row + 8] = __float2half_rn(acc[mi][ni][3]);
        }
    __syncthreads();

    // ===== G4: out = relu(A_norm @ t + b2) =====
    gemm_h(sA, sB, acc, wm, wn, lane);
    #pragma unroll
    for (int mi = 0; mi < 4; mi++)
        #pragma unroll
        for (int ni = 0; ni < 4; ni++) {
            int row = wm * 64 + mi * 16 + r, col = wn * 32 + ni * 8 + c2;
            if (row < NN) {
                float2 v0 = make_float2(fmaxf(acc[mi][ni][0] + sb2[col], 0.f),
                                        fmaxf(acc[mi][ni][1] + sb2[col + 1], 0.f));
                *reinterpret_cast<float2*>(ob + (size_t)row * HH + col) = v0;
            }
            if (row + 8 < NN) {
                float2 v1 = make_float2(fmaxf(acc[mi][ni][2] + sb2[col], 0.f),
                                        fmaxf(acc[mi][ni][3] + sb2[col + 1], 0.f));
                *reinterpret_cast<float2*>(ob + (size_t)(row + 8) * HH + col) = v1;
            }
        }
}

extern "C" void kernel_launch(void* const* d_in, const int* in_sizes, int n_in,
                              void* d_out, int out_size)
{
    const float* a  = (const float*)d_in[0];
    const float* f  = (const float*)d_in[1];
    const float* W1 = (const float*)d_in[2];
    const float* b1 = (const float*)d_in[3];
    const float* W2 = (const float*)d_in[4];
    const float* b2 = (const float*)d_in[5];
    float* out = (float*)d_out;

    int batch = in_sizes[0] / (NN * NN);

    cudaFuncSetAttribute(gcn_mma, cudaFuncAttributeMaxDynamicSharedMemorySize, (int)SMEM_BYTES);
    gcn_mma<<<batch, NTHREADS, SMEM_BYTES>>>(a, f, W1, b1, W2, b2, out);
}

// round 9
// speedup vs baseline: 1.8823x; 1.0268x over previous
#include <cuda_runtime.h>
#include <cuda_fp16.h>
#include <cstdint>

#define NN 116
#define HH 128
#define NTHREADS 256
#define STR 136            // row stride in HALFS; 272B rows -> ldmatrix conflict-free

static constexpr size_t SMEM_BYTES = (size_t)(3 * 128 * STR) * sizeof(__half);  // 104448

__device__ __forceinline__ uint32_t smem_u32(const void* p) {
    uint32_t a;
    asm("{ .reg .u64 t; cvta.to.shared.u64 t, %1; cvt.u32.u64 %0, t; }" : "=r"(a) : "l"(p));
    return a;
}

#define LDSM4(r0, r1, r2, r3, addr)                                           \
    asm volatile("ldmatrix.sync.aligned.m8n8.x4.shared.b16 {%0,%1,%2,%3}, [%4];" \
                 : "=r"(r0), "=r"(r1), "=r"(r2), "=r"(r3) : "r"(addr))

#define MMA_F16(d, a, b)                                                      \
    asm volatile(                                                             \
        "mma.sync.aligned.m16n8k16.row.col.f32.f16.f16.f32 "                  \
        "{%0,%1,%2,%3}, {%4,%5,%6,%7}, {%8,%9}, {%0,%1,%2,%3};"               \
        : "+f"(d[0]), "+f"(d[1]), "+f"(d[2]), "+f"(d[3])                      \
        : "r"(a[0]), "r"(a[1]), "r"(a[2]), "r"(a[3]), "r"(b[0]), "r"(b[1]))

// 128x128x128 fp16 GEMM; 8 warps in 2x4 grid; warp tile 64(m) x 32(n).
// Fragments via ldmatrix.x4: per k-step 4 LDSM (A) + 2 LDSM (B) + 16 MMA.
__device__ __forceinline__ void gemm_h(const __half* __restrict__ Aop,
                                       const __half* __restrict__ Bop,
                                       float acc[4][4][4],
                                       int wm, int wn, int lane)
{
    #pragma unroll
    for (int mi = 0; mi < 4; mi++)
        #pragma unroll
        for (int ni = 0; ni < 4; ni++)
            #pragma unroll
            for (int q = 0; q < 4; q++) acc[mi][ni][q] = 0.f;

    const int t = lane >> 3, ri = lane & 7;

    // A tile t: rows (t&1)*8 + ri, k-half (t>>1)
    uint32_t aAm[4];
    #pragma unroll
    for (int mi = 0; mi < 4; mi++)
        aAm[mi] = smem_u32(Aop + (wm * 64 + mi * 16 + (t & 1) * 8 + ri) * STR) + (t >> 1) * 16;
    // B tile t: n-rows (t>>1)*8 + ri, k-half (t&1)
    uint32_t aBp[2];
    #pragma unroll
    for (int pi = 0; pi < 2; pi++)
        aBp[pi] = smem_u32(Bop + (wn * 32 + pi * 16 + (t >> 1) * 8 + ri) * STR) + (t & 1) * 16;

    #pragma unroll
    for (int ks = 0; ks < 8; ks++) {
        const uint32_t kb = ks * 32;     // 16 halfs = 32 bytes
        uint32_t fa[4][4], fb[4][2];
        #pragma unroll
        for (int mi = 0; mi < 4; mi++)
            LDSM4(fa[mi][0], fa[mi][1], fa[mi][2], fa[mi][3], aAm[mi] + kb);
        #pragma unroll
        for (int pi = 0; pi < 2; pi++)
            LDSM4(fb[2 * pi][0], fb[2 * pi][1], fb[2 * pi + 1][0], fb[2 * pi + 1][1],
                  aBp[pi] + kb);
        #pragma unroll
        for (int mi = 0; mi < 4; mi++)
            #pragma unroll
            for (int ni = 0; ni < 4; ni++)
                MMA_F16(acc[mi][ni], fa[mi], fb[ni]);
    }
}

__global__ __launch_bounds__(NTHREADS, 2)
void gcn_mma(const float* __restrict__ ga, const float* __restrict__ gf,
             const float* __restrict__ gW1, const float* __restrict__ gb1,
             const float* __restrict__ gW2, const float* __restrict__ gb2,
             float* __restrict__ gout)
{
    extern __shared__ __half sh[];
    __half* sA = sh;                  // A_norm    [128][STR]  (A-layout [m][k])
    __half* sX = sh + 128 * STR;      // f -> h    [128][STR]  (A-layout)
    __half* sB = sh + 2 * 128 * STR;  // W1/g/W2/t [128][STR]  (B-layout [n][k])
    __shared__ float sd[128], sb1[128], sb2[128];

    const int tid = threadIdx.x;
    const int wid = tid >> 5, lane = tid & 31;
    const int wm = wid & 1, wn = wid >> 1;   // 2x4 warp grid -> 64x32 tiles
    const int b = blockIdx.x;
    const float* ab = ga + (size_t)b * NN * NN;
    const float* fg = gf + (size_t)b * NN * NN;
    float*       ob = gout + (size_t)b * NN * HH;

    // ---- zero all operand buffers ----
    for (int i = tid; i < 6528; i += NTHREADS)
        reinterpret_cast<uint4*>(sh)[i] = make_uint4(0u, 0u, 0u, 0u);
    if (tid < 128) { sb1[tid] = __ldg(gb1 + tid); sb2[tid] = __ldg(gb2 + tid); }

    // ---- pass 1: rowsums of |a| straight from gmem -> d ----
    for (int row = wid; row < NN; row += 8) {
        const float* rp = ab + row * NN;
        float s = 0.f;
        #pragma unroll
        for (int jj = 0; jj < 4; jj++) {
            int j = lane + jj * 32;
            if (j < NN) s += fabsf(__ldg(rp + j));
        }
        #pragma unroll
        for (int o = 16; o; o >>= 1) s += __shfl_xor_sync(0xffffffffu, s, o);
        if (!lane) sd[row] = rsqrtf(s + 1.0f);
    }
    __syncthreads();

    // ---- pass 2: A_norm(half), f(half), W1(half, [n][k]) ----
    for (int idx = tid; idx < NN * NN; idx += NTHREADS) {
        int i = idx / NN, j = idx - i * NN;
        float v = fabsf(__ldg(ab + idx)) + (i == j ? 1.0f : 0.0f);
        sA[i * STR + j] = __float2half_rn(sd[i] * sd[j] * v);
        sX[i * STR + j] = __float2half_rn(__ldg(fg + idx));
    }
    for (int idx = tid; idx < NN * HH; idx += NTHREADS) {
        int k = idx >> 7, n = idx & 127;
        sB[n * STR + k] = __float2half_rn(__ldg(gW1 + idx));
    }
    __syncthreads();

    const int r = lane >> 2, c2 = (lane & 3) * 2;
    float acc[4][4][4];

    // ===== G1: g = f @ W1 =====
    gemm_h(sX, sB, acc, wm, wn, lane);
    __syncthreads();                          // all warps done reading W1
    #pragma unroll
    for (int mi = 0; mi < 4; mi++)
        #pragma unroll
        for (int ni = 0; ni < 4; ni++) {
            int row = wm * 64 + mi * 16 + r, col = wn * 32 + ni * 8 + c2;
            sB[col * STR + row]           = __float2half_rn(acc[mi][ni][0]);
            sB[(col + 1) * STR + row]     = __float2half_rn(acc[mi][ni][1]);
            sB[col * STR + row + 8]       = __float2half_rn(acc[mi][ni][2]);
            sB[(col + 1) * STR + row + 8] = __float2half_rn(acc[mi][ni][3]);
        }
    __syncthreads();

    // ===== G2: h = relu(A_norm @ g + b1) =====
    gemm_h(sA, sB, acc, wm, wn, lane);
    __syncthreads();                          // all warps done reading g
    #pragma unroll
    for (int mi = 0; mi < 4; mi++)
        #pragma unroll
        for (int ni = 0; ni < 4; ni++) {
            int row = wm * 64 + mi * 16 + r, col = wn * 32 + ni * 8 + c2;
            *reinterpret_cast<__half2*>(sX + row * STR + col) =
                __floats2half2_rn(fmaxf(acc[mi][ni][0] + sb1[col], 0.f),
                                  fmaxf(acc[mi][ni][1] + sb1[col + 1], 0.f));
            *reinterpret_cast<__half2*>(sX + (row + 8) * STR + col) =
                __floats2half2_rn(fmaxf(acc[mi][ni][2] + sb1[col], 0.f),
                                  fmaxf(acc[mi][ni][3] + sb1[col + 1], 0.f));
        }
    for (int idx = tid; idx < HH * HH; idx += NTHREADS) {
        int k = idx >> 7, n = idx & 127;
        sB[n * STR + k] = __float2half_rn(__ldg(gW2 + idx));
    }
    __syncthreads();

    // ===== G3: t = h @ W2 =====
    gemm_h(sX, sB, acc, wm, wn, lane);
    __syncthreads();                          // all warps done reading W2
    #pragma unroll
    for (int mi = 0; mi < 4; mi++)
        #pragma unroll
        for (int ni = 0; ni < 4; ni++) {
            int row = wm * 64 + mi * 16 + r, col = wn * 32 + ni * 8 + c2;
            sB[col * STR + row]           = __float2half_rn(acc[mi][ni][0]);
            sB[(col + 1) * STR + row]     = __float2half_rn(acc[mi][ni][1]);
            sB[col * STR + row + 8]       = __float2half_rn(acc[mi][ni][2]);
            sB[(col + 1) * STR + row + 8] = __float2half_rn(acc[mi][ni][3]);
        }
    __syncthreads();

    // ===== G4: out = relu(A_norm @ t + b2) =====
    gemm_h(sA, sB, acc, wm, wn, lane);
    #pragma unroll
    for (int mi = 0; mi < 4; mi++)
        #pragma unroll
        for (int ni = 0; ni < 4; ni++) {
            int row = wm * 64 + mi * 16 + r, col = wn * 32 + ni * 8 + c2;
            if (row < NN) {
                float2 v0 = make_float2(fmaxf(acc[mi][ni][0] + sb2[col], 0.f),
                                        fmaxf(acc[mi][ni][1] + sb2[col + 1], 0.f));
                *reinterpret_cast<float2*>(ob + (size_t)row * HH + col) = v0;
            }
            if (row + 8 < NN) {
                float2 v1 = make_float2(fmaxf(acc[mi][ni][2] + sb2[col], 0.f),
                                        fmaxf(acc[mi][ni][3] + sb2[col + 1], 0.f));
                *reinterpret_cast<float2*>(ob + (size_t)(row + 8) * HH + col) = v1;
            }
        }
}

extern "C" void kernel_launch(void* const* d_in, const int* in_sizes, int n_in,
                              void* d_out, int out_size)
{
    const float* a  = (const float*)d_in[0];
    const float* f  = (const float*)d_in[1];
    const float* W1 = (const float*)d_in[2];
    const float* b1 = (const float*)d_in[3];
    const float* W2 = (const float*)d_in[4];
    const float* b2 = (const float*)d_in[5];
    float* out = (float*)d_out;

    int batch = in_sizes[0] / (NN * NN);

    cudaFuncSetAttribute(gcn_mma, cudaFuncAttributeMaxDynamicSharedMemorySize, (int)SMEM_BYTES);
    gcn_mma<<<batch, NTHREADS, SMEM_BYTES>>>(a, f, W1, b1, W2, b2, out);
}

// round 10
// speedup vs baseline: 2.3230x; 1.2341x over previous
#include <cuda_runtime.h>
#include <cuda_fp16.h>
#include <cstdint>

#define NN 116
#define HH 128
#define NTHREADS 512
#define STR 136            // row stride in HALFS; 272B rows -> ldmatrix conflict-free

static constexpr size_t SMEM_BYTES = (size_t)(3 * 128 * STR) * sizeof(__half);  // 104448

__device__ __forceinline__ uint32_t smem_u32(const void* p) {
    uint32_t a;
    asm("{ .reg .u64 t; cvta.to.shared.u64 t, %1; cvt.u32.u64 %0, t; }" : "=r"(a) : "l"(p));
    return a;
}

#define LDSM4(r0, r1, r2, r3, addr)                                           \
    asm volatile("ldmatrix.sync.aligned.m8n8.x4.shared.b16 {%0,%1,%2,%3}, [%4];" \
                 : "=r"(r0), "=r"(r1), "=r"(r2), "=r"(r3) : "r"(addr))

#define MMA_F16(d, a, b)                                                      \
    asm volatile(                                                             \
        "mma.sync.aligned.m16n8k16.row.col.f32.f16.f16.f32 "                  \
        "{%0,%1,%2,%3}, {%4,%5,%6,%7}, {%8,%9}, {%0,%1,%2,%3};"               \
        : "+f"(d[0]), "+f"(d[1]), "+f"(d[2]), "+f"(d[3])                      \
        : "r"(a[0]), "r"(a[1]), "r"(a[2]), "r"(a[3]), "r"(b[0]), "r"(b[1]))

// 128x128x128 fp16 GEMM; 16 warps in 4x4 grid; warp tile 32(m) x 32(n).
// Per k-step: 2 LDSM.x4 (A) + 2 LDSM.x4 (B) + 8 MMA.
__device__ __forceinline__ void gemm_h(const __half* __restrict__ Aop,
                                       const __half* __restrict__ Bop,
                                       float acc[2][4][4],
                                       int wm, int wn, int lane)
{
    #pragma unroll
    for (int mi = 0; mi < 2; mi++)
        #pragma unroll
        for (int ni = 0; ni < 4; ni++)
            #pragma unroll
            for (int q = 0; q < 4; q++) acc[mi][ni][q] = 0.f;

    const int t = lane >> 3, ri = lane & 7;

    // A tile mi: rows wm*32 + mi*16 + (t&1)*8 + ri, k-half (t>>1)
    uint32_t aAm[2];
    #pragma unroll
    for (int mi = 0; mi < 2; mi++)
        aAm[mi] = smem_u32(Aop + (wm * 32 + mi * 16 + (t & 1) * 8 + ri) * STR) + (t >> 1) * 16;
    // B pair pi: n-rows wn*32 + pi*16 + (t>>1)*8 + ri, k-half (t&1)
    uint32_t aBp[2];
    #pragma unroll
    for (int pi = 0; pi < 2; pi++)
        aBp[pi] = smem_u32(Bop + (wn * 32 + pi * 16 + (t >> 1) * 8 + ri) * STR) + (t & 1) * 16;

    #pragma unroll
    for (int ks = 0; ks < 8; ks++) {
        const uint32_t kb = ks * 32;     // 16 halfs = 32 bytes
        uint32_t fa[2][4], fb[4][2];
        #pragma unroll
        for (int mi = 0; mi < 2; mi++)
            LDSM4(fa[mi][0], fa[mi][1], fa[mi][2], fa[mi][3], aAm[mi] + kb);
        #pragma unroll
        for (int pi = 0; pi < 2; pi++)
            LDSM4(fb[2 * pi][0], fb[2 * pi][1], fb[2 * pi + 1][0], fb[2 * pi + 1][1],
                  aBp[pi] + kb);
        #pragma unroll
        for (int mi = 0; mi < 2; mi++)
            #pragma unroll
            for (int ni = 0; ni < 4; ni++)
                MMA_F16(acc[mi][ni], fa[mi], fb[ni]);
    }
}

__global__ __launch_bounds__(NTHREADS, 2)
void gcn_mma(const float* __restrict__ ga, const float* __restrict__ gf,
             const float* __restrict__ gW1, const float* __restrict__ gb1,
             const float* __restrict__ gW2, const float* __restrict__ gb2,
             float* __restrict__ gout)
{
    extern __shared__ __half sh[];
    __half* sA = sh;                  // A_norm    [128][STR]  (A-layout [m][k])
    __half* sX = sh + 128 * STR;      // f -> h    [128][STR]  (A-layout)
    __half* sB = sh + 2 * 128 * STR;  // W1/g/W2/t [128][STR]  (B-layout [n][k])
    __shared__ float sd[128], sb1[128], sb2[128];

    const int tid = threadIdx.x;
    const int wid = tid >> 5, lane = tid & 31;
    const int wm = wid & 3, wn = wid >> 2;   // 4x4 warp grid -> 32x32 tiles
    const int b = blockIdx.x;
    const float* ab = ga + (size_t)b * NN * NN;
    const float* fg = gf + (size_t)b * NN * NN;
    float*       ob = gout + (size_t)b * NN * HH;

    // ---- zero all operand buffers ----
    for (int i = tid; i < 6528; i += NTHREADS)
        reinterpret_cast<uint4*>(sh)[i] = make_uint4(0u, 0u, 0u, 0u);
    if (tid < 128) { sb1[tid] = __ldg(gb1 + tid); sb2[tid] = __ldg(gb2 + tid); }

    // ---- pass 1: rowsums of |a| straight from gmem -> d ----
    for (int row = wid; row < NN; row += 16) {
        const float* rp = ab + row * NN;
        float s = 0.f;
        #pragma unroll
        for (int jj = 0; jj < 4; jj++) {
            int j = lane + jj * 32;
            if (j < NN) s += fabsf(__ldg(rp + j));
        }
        #pragma unroll
        for (int o = 16; o; o >>= 1) s += __shfl_xor_sync(0xffffffffu, s, o);
        if (!lane) sd[row] = rsqrtf(s + 1.0f);
    }
    __syncthreads();

    // ---- pass 2: A_norm(half), f(half), W1(half, [n][k]) ----
    for (int idx = tid; idx < NN * NN; idx += NTHREADS) {
        int i = idx / NN, j = idx - i * NN;
        float v = fabsf(__ldg(ab + idx)) + (i == j ? 1.0f : 0.0f);
        sA[i * STR + j] = __float2half_rn(sd[i] * sd[j] * v);
        sX[i * STR + j] = __float2half_rn(__ldg(fg + idx));
    }
    for (int idx = tid; idx < NN * HH; idx += NTHREADS) {
        int k = idx >> 7, n = idx & 127;
        sB[n * STR + k] = __float2half_rn(__ldg(gW1 + idx));
    }
    __syncthreads();

    const int r = lane >> 2, c2 = (lane & 3) * 2;
    float acc[2][4][4];

    // ===== G1: g = f @ W1 =====
    gemm_h(sX, sB, acc, wm, wn, lane);
    __syncthreads();                          // all warps done reading W1
    #pragma unroll
    for (int mi = 0; mi < 2; mi++)
        #pragma unroll
        for (int ni = 0; ni < 4; ni++) {
            int row = wm * 32 + mi * 16 + r, col = wn * 32 + ni * 8 + c2;
            sB[col * STR + row]           = __float2half_rn(acc[mi][ni][0]);
            sB[(col + 1) * STR + row]     = __float2half_rn(acc[mi][ni][1]);
            sB[col * STR + row + 8]       = __float2half_rn(acc[mi][ni][2]);
            sB[(col + 1) * STR + row + 8] = __float2half_rn(acc[mi][ni][3]);
        }
    __syncthreads();

    // ===== G2: h = relu(A_norm @ g + b1) =====
    gemm_h(sA, sB, acc, wm, wn, lane);
    __syncthreads();                          // all warps done reading g
    #pragma unroll
    for (int mi = 0; mi < 2; mi++)
        #pragma unroll
        for (int ni = 0; ni < 4; ni++) {
            int row = wm * 32 + mi * 16 + r, col = wn * 32 + ni * 8 + c2;
            *reinterpret_cast<__half2*>(sX + row * STR + col) =
                __floats2half2_rn(fmaxf(acc[mi][ni][0] + sb1[col], 0.f),
                                  fmaxf(acc[mi][ni][1] + sb1[col + 1], 0.f));
            *reinterpret_cast<__half2*>(sX + (row + 8) * STR + col) =
                __floats2half2_rn(fmaxf(acc[mi][ni][2] + sb1[col], 0.f),
                                  fmaxf(acc[mi][ni][3] + sb1[col + 1], 0.f));
        }
    for (int idx = tid; idx < HH * HH; idx += NTHREADS) {
        int k = idx >> 7, n = idx & 127;
        sB[n * STR + k] = __float2half_rn(__ldg(gW2 + idx));
    }
    __syncthreads();

    // ===== G3: t = h @ W2 =====
    gemm_h(sX, sB, acc, wm, wn, lane);
    __syncthreads();                          // all warps done reading W2
    #pragma unroll
    for (int mi = 0; mi < 2; mi++)
        #pragma unroll
        for (int ni = 0; ni < 4; ni++) {
            int row = wm * 32 + mi * 16 + r, col = wn * 32 + ni * 8 + c2;
            sB[col * STR + row]           = __float2half_rn(acc[mi][ni][0]);
            sB[(col + 1) * STR + row]     = __float2half_rn(acc[mi][ni][1]);
            sB[col * STR + row + 8]       = __float2half_rn(acc[mi][ni][2]);
            sB[(col + 1) * STR + row + 8] = __float2half_rn(acc[mi][ni][3]);
        }
    __syncthreads();

    // ===== G4: out = relu(A_norm @ t + b2) =====
    gemm_h(sA, sB, acc, wm, wn, lane);
    #pragma unroll
    for (int mi = 0; mi < 2; mi++)
        #pragma unroll
        for (int ni = 0; ni < 4; ni++) {
            int row = wm * 32 + mi * 16 + r, col = wn * 32 + ni * 8 + c2;
            if (row < NN) {
                float2 v0 = make_float2(fmaxf(acc[mi][ni][0] + sb2[col], 0.f),
                                        fmaxf(acc[mi][ni][1] + sb2[col + 1], 0.f));
                *reinterpret_cast<float2*>(ob + (size_t)row * HH + col) = v0;
            }
            if (row + 8 < NN) {
                float2 v1 = make_float2(fmaxf(acc[mi][ni][2] + sb2[col], 0.f),
                                        fmaxf(acc[mi][ni][3] + sb2[col + 1], 0.f));
                *reinterpret_cast<float2*>(ob + (size_t)(row + 8) * HH + col) = v1;
            }
        }
}

extern "C" void kernel_launch(void* const* d_in, const int* in_sizes, int n_in,
                              void* d_out, int out_size)
{
    const float* a  = (const float*)d_in[0];
    const float* f  = (const float*)d_in[1];
    const float* W1 = (const float*)d_in[2];
    const float* b1 = (const float*)d_in[3];
    const float* W2 = (const float*)d_in[4];
    const float* b2 = (const float*)d_in[5];
    float* out = (float*)d_out;

    int batch = in_sizes[0] / (NN * NN);

    cudaFuncSetAttribute(gcn_mma, cudaFuncAttributeMaxDynamicSharedMemorySize, (int)SMEM_BYTES);
    gcn_mma<<<batch, NTHREADS, SMEM_BYTES>>>(a, f, W1, b1, W2, b2, out);
}